// round 8
// baseline (speedup 1.0000x reference)
#include <cuda_runtime.h>
#include <cuda_fp16.h>

// FreqGrid triplane encoder. R8: overlap DRAM-bound transpose with L2-bound
// gather by splitting per-plane:
//   K1: transpose plane 0
//   K2: fused -- 1/3 of blocks transpose planes 1,2 (DRAM) while 2/3 run the
//       plane-0 gather pass (L2). Disjoint data, no sync needed.
//   K3: gather pass for planes 1,2; accumulates into out.
// Gather core = R5 (best measured): half-warp per point, padded grid,
// compile-time corner offsets, fp16 storage, HFMA2 blend.

#define RR 256
#define CHN 128
#define PLANE_ELEMS (RR * RR)              // 65536
#define GT_ELEMS (3 * PLANE_ELEMS * CHN)   // 48 MB of halfs
#define GT_PAD (33024)                     // covers +row+texel overrun

__device__ __half g_grid_t[GT_ELEMS + GT_PAD];

#define PI_OVER_R 0.01227184630308513f     // pi/256
#define KC        0.006135923151542565f    // pi/512

// swizzled half-index for (spatial row s, channel ch) in a 64x128 tile
__device__ __forceinline__ int sw_idx(int s, int ch) {
    int chunk = (ch >> 3) ^ ((s >> 2) & 15);
    return s * 128 + (chunk << 3) + (ch & 7);
}

// ---------------------------------------------------------------------------
// Transpose one 64-spatial x 128-channel tile of plane p at spatial base s0
// ---------------------------------------------------------------------------
__device__ __forceinline__ void transpose_tile(const float* __restrict__ g,
                                               __half* __restrict__ sm_tile,
                                               int p, int s0, int tid) {
    const float* in = g + (size_t)p * CHN * PLANE_ELEMS + s0;

    #pragma unroll
    for (int i = 0; i < 8; i++) {
        int u  = i * 256 + tid;
        int q  = u & 15;     // float4 index within 64 spatial
        int ch = u >> 4;     // 0..127
        float4 f = *(const float4*)(in + (size_t)ch * PLANE_ELEMS + 4 * q);
        sm_tile[sw_idx(4 * q + 0, ch)] = __float2half_rn(f.x);
        sm_tile[sw_idx(4 * q + 1, ch)] = __float2half_rn(f.y);
        sm_tile[sw_idx(4 * q + 2, ch)] = __float2half_rn(f.z);
        sm_tile[sw_idx(4 * q + 3, ch)] = __float2half_rn(f.w);
    }
    __syncthreads();

    __half* outp = g_grid_t + (size_t)p * PLANE_ELEMS * CHN + (size_t)s0 * CHN;
    #pragma unroll
    for (int i = 0; i < 4; i++) {
        int u  = i * 256 + tid;
        int c8 = u & 15;     // channel octet 0..15
        int s  = u >> 4;     // 0..63
        int chunk = c8 ^ ((s >> 2) & 15);
        uint4 val = *(const uint4*)&sm_tile[s * 128 + (chunk << 3)];
        *(uint4*)(outp + s * CHN + 8 * c8) = val;
    }
}

__global__ void __launch_bounds__(256) transpose0_kernel(const float* __restrict__ g) {
    __shared__ __half tile[64 * 128];
    transpose_tile(g, tile, 0, blockIdx.x << 6, threadIdx.x);
}

// ---------------------------------------------------------------------------
// Gather building blocks
// ---------------------------------------------------------------------------
__device__ __forceinline__ void load_corners(const uint4* __restrict__ gb,
                                             int off, uint4* v) {
    v[0] = __ldg(&gb[off]);
    v[1] = __ldg(&gb[off + 16]);       // +x texel
    v[2] = __ldg(&gb[off + 4096]);     // +y row
    v[3] = __ldg(&gb[off + 4112]);
}

__device__ __forceinline__ void blend_plane(const uint4* v, float wxd, float wyd,
                                            float kdd, const float* frh,
                                            float& acc0, float& acc1) {
    __half2 w00 = __float2half2_rn((1.0f - wxd) * (1.0f - wyd));
    __half2 w01 = __float2half2_rn(wxd * (1.0f - wyd));
    __half2 w10 = __float2half2_rn((1.0f - wxd) * wyd);
    __half2 w11 = __float2half2_rn(wxd * wyd);

    const __half2* c0 = (const __half2*)&v[0];
    const __half2* c1 = (const __half2*)&v[1];
    const __half2* c2 = (const __half2*)&v[2];
    const __half2* c3 = (const __half2*)&v[3];

    #pragma unroll
    for (int q = 0; q < 4; q++) {
        __half2 cf = __hmul2(w00, c0[q]);
        cf = __hfma2(w01, c1[q], cf);
        cf = __hfma2(w10, c2[q], cf);
        cf = __hfma2(w11, c3[q], cf);
        float2 f = __half22float2(cf);
        acc0 = fmaf(f.x, __cosf(kdd * frh[2 * q]),     acc0);
        acc1 = fmaf(f.y, __cosf(kdd * frh[2 * q + 1]), acc1);
    }
}

__device__ __forceinline__ void load_frh(const float* __restrict__ freqs,
                                         int cl, float* frh) {
    #pragma unroll
    for (int j = 0; j < 8; j++) {
        float fq = __ldg(&freqs[8 * cl + j]);
        fq = fminf(fmaxf(fq, 0.0f), 1.0f);
        frh[j] = exp2f(fq * 8.0f) - 0.5f;
    }
}

// ---------------------------------------------------------------------------
// Pass 0: plane 0 only (ix=pt1, iy=pt2, basis uses kd0). Writes out.
// Ping-pong double buffer across iterations.
// ---------------------------------------------------------------------------
template <int PAIRS>
__device__ __forceinline__ void gather_pass0(int warp, int lane,
                                             const float* __restrict__ coords,
                                             const float* __restrict__ freqs,
                                             float* __restrict__ out, int N) {
    const int sub = lane >> 4;
    const int cl  = lane & 15;

    float frh[8];
    load_frh(freqs, cl, frh);

    const uint4* __restrict__ gb = (const uint4*)g_grid_t;
    const int base0 = warp * (2 * PAIRS);

    int off[PAIRS];
    float wx[PAIRS], wy[PAIRS], kd[PAIRS];
    #pragma unroll
    for (int t = 0; t < PAIRS; t++) {
        int n = min(base0 + 2 * t + sub, N - 1);
        float pt0 = fmaf(__ldg(&coords[3 * n + 0]), 127.5f, 127.5f);
        float pt1 = fmaf(__ldg(&coords[3 * n + 1]), 127.5f, 127.5f);
        float pt2 = fmaf(__ldg(&coords[3 * n + 2]), 127.5f, 127.5f);
        kd[t] = fmaf(pt0, PI_OVER_R, KC);
        int x0 = (int)pt1, y0 = (int)pt2;
        wx[t] = pt1 - (float)x0;
        wy[t] = pt2 - (float)y0;
        off[t] = (((y0 << 8) + x0) << 4) + cl;
    }

    uint4 va[4], vb[4];
    load_corners(gb, off[0], va);
    #pragma unroll
    for (int t = 0; t < PAIRS; t++) {
        uint4* cur = (t & 1) ? vb : va;
        uint4* nxt = (t & 1) ? va : vb;
        if (t + 1 < PAIRS) load_corners(gb, off[t + 1], nxt);

        float a0 = 0.0f, a1 = 0.0f;
        blend_plane(cur, wx[t], wy[t], kd[t], frh, a0, a1);

        int n = base0 + 2 * t + sub;
        if (n < N) out[n * 16 + cl] = 2.0f * (a0 + a1);
    }
}

// ---------------------------------------------------------------------------
// K2: fused kernel. blockIdx%3==0 -> transpose tile of planes 1,2;
//     else -> plane-0 gather chunk.
// ---------------------------------------------------------------------------
template <int PAIRS>
__global__ void __launch_bounds__(256)
mixed_kernel(const float* __restrict__ g,
             const float* __restrict__ coords,
             const float* __restrict__ freqs,
             float* __restrict__ out, int N) {
    __shared__ __half tile[64 * 128];
    const int b = blockIdx.x;
    if (b % 3 == 0) {
        int t  = b / 3;                    // 0..2047
        int p  = 1 + (t >> 10);            // planes 1,2
        int s0 = (t & 1023) << 6;
        transpose_tile(g, tile, p, s0, threadIdx.x);
    } else {
        int gidx = (b / 3) * 2 + (b % 3) - 1;   // 0..4095
        int warp = gidx * 8 + ((int)threadIdx.x >> 5);
        gather_pass0<PAIRS>(warp, threadIdx.x & 31, coords, freqs, out, N);
    }
}

// ---------------------------------------------------------------------------
// K3: planes 1,2 gather pass; accumulates into out.
// ---------------------------------------------------------------------------
template <int PAIRS>
__global__ void __launch_bounds__(256)
gather12_kernel(const float* __restrict__ coords,
                const float* __restrict__ freqs,
                float* __restrict__ out, int N) {
    const int warp = (blockIdx.x * blockDim.x + threadIdx.x) >> 5;
    const int lane = threadIdx.x & 31;
    const int sub  = lane >> 4;
    const int cl   = lane & 15;

    float frh[8];
    load_frh(freqs, cl, frh);

    const uint4* __restrict__ gb = (const uint4*)g_grid_t;
    const int base0 = warp * (2 * PAIRS);

    #pragma unroll
    for (int t = 0; t < PAIRS; t++) {
        const int nb = base0 + 2 * t;
        if (nb >= N) return;
        const int n = min(nb + sub, N - 1);

        float pt0 = fmaf(__ldg(&coords[3 * n + 0]), 127.5f, 127.5f);
        float pt1 = fmaf(__ldg(&coords[3 * n + 1]), 127.5f, 127.5f);
        float pt2 = fmaf(__ldg(&coords[3 * n + 2]), 127.5f, 127.5f);

        float kd1 = fmaf(pt1, PI_OVER_R, KC);
        float kd2 = fmaf(pt2, PI_OVER_R, KC);

        // plane 1: (ix,iy)=(pt0,pt2); plane 2: (ix,iy)=(pt0,pt1)
        int x0b = (int)pt0, y0b = (int)pt2;
        int x0c = (int)pt0, y0c = (int)pt1;
        float wxb = pt0 - (float)x0b, wyb = pt2 - (float)y0b;
        float wxc = pt0 - (float)x0c, wyc = pt1 - (float)y0c;

        int offb = ((PLANE_ELEMS + (y0b << 8) + x0b) << 4) + cl;
        int offc = ((2 * PLANE_ELEMS + (y0c << 8) + x0c) << 4) + cl;

        uint4 va[4], vb[4];
        load_corners(gb, offb, va);
        load_corners(gb, offc, vb);

        float a0 = 0.0f, a1 = 0.0f;
        blend_plane(va, wxb, wyb, kd1, frh, a0, a1);
        blend_plane(vb, wxc, wyc, kd2, frh, a0, a1);

        if (nb + sub < N) {
            float* dst = &out[n * 16 + cl];
            *dst = fmaf(2.0f, a0 + a1, *dst);
        }
    }
}

// ---------------------------------------------------------------------------
// Harness entry
// ---------------------------------------------------------------------------
extern "C" void kernel_launch(void* const* d_in, const int* in_sizes, int n_in,
                              void* d_out, int out_size) {
    const float* coords = (const float*)d_in[0];
    const float* grid   = (const float*)d_in[1];
    const float* freqs  = (const float*)d_in[2];
    float* out = (float*)d_out;

    const int N = in_sizes[0] / 3;

    constexpr int PAIRS = 4;                       // 8 points per warp
    const int pts_per_warp = 2 * PAIRS;
    const int warps = (N + pts_per_warp - 1) / pts_per_warp;
    const int gather_blocks = (warps + 7) / 8;     // 8 warps per block (=4096)

    // K1: transpose plane 0
    transpose0_kernel<<<PLANE_ELEMS / 64, 256>>>(grid);

    // K2: transpose planes 1,2 (1/3 of blocks) || plane-0 gather (2/3)
    mixed_kernel<PAIRS><<<3 * gather_blocks / 2, 256>>>(grid, coords, freqs, out, N);

    // K3: planes 1,2 gather, accumulate
    gather12_kernel<PAIRS><<<gather_blocks, 256>>>(coords, freqs, out, N);
}

// round 9
// speedup vs baseline: 1.1801x; 1.1801x over previous
#include <cuda_runtime.h>
#include <cuda_fp16.h>

// FreqGrid triplane encoder. R9 = best-of breed:
//  - gather: R5 2-stage plane pipeline (regs free-floating, no coord prefetch),
//    R6 padded grid + compile-time corner offsets (no boundary selects),
//    PAIRS=8 to amortize the frh prologue
//  - transpose: R5 swizzled 64x128 tiles + __ldcs on the dead-after-read fp32
//    source so it doesn't evict the fp16 destination from L2

#define RR 256
#define CHN 128
#define PLANE_ELEMS (RR * RR)              // 65536
#define GT_ELEMS (3 * PLANE_ELEMS * CHN)   // 48 MB of halfs
#define GT_PAD (33024)                     // covers +row+texel overrun (zeroed)

__device__ __half g_grid_t[GT_ELEMS + GT_PAD];

#define PI_OVER_R 0.01227184630308513f     // pi/256
#define KC        0.006135923151542565f    // pi/512

// swizzled half-index for (spatial row s, channel ch) in a 64x128 tile
__device__ __forceinline__ int sw_idx(int s, int ch) {
    int chunk = (ch >> 3) ^ ((s >> 2) & 15);
    return s * 128 + (chunk << 3) + (ch & 7);
}

// ---------------------------------------------------------------------------
// Transpose + quantize: in[p][ch][s] -> g_grid_t[p][s][ch] (fp16)
// ---------------------------------------------------------------------------
__global__ void __launch_bounds__(256) transpose_kernel(const float* __restrict__ g) {
    __shared__ __half tile[64 * 128];
    const int p  = blockIdx.y;
    const int s0 = blockIdx.x << 6;
    const int tid = threadIdx.x;

    const float* in = g + (size_t)p * CHN * PLANE_ELEMS + s0;

    #pragma unroll
    for (int i = 0; i < 8; i++) {
        int u  = i * 256 + tid;
        int q  = u & 15;     // float4 index within 64 spatial
        int ch = u >> 4;     // 0..127
        // evict-first: source is dead after this read; keep L2 for the dest
        float4 f = __ldcs((const float4*)(in + (size_t)ch * PLANE_ELEMS + 4 * q));
        tile[sw_idx(4 * q + 0, ch)] = __float2half_rn(f.x);
        tile[sw_idx(4 * q + 1, ch)] = __float2half_rn(f.y);
        tile[sw_idx(4 * q + 2, ch)] = __float2half_rn(f.z);
        tile[sw_idx(4 * q + 3, ch)] = __float2half_rn(f.w);
    }
    __syncthreads();

    __half* outp = g_grid_t + (size_t)p * PLANE_ELEMS * CHN + (size_t)s0 * CHN;
    #pragma unroll
    for (int i = 0; i < 4; i++) {
        int u  = i * 256 + tid;
        int c8 = u & 15;     // channel octet 0..15
        int s  = u >> 4;     // 0..63
        int chunk = c8 ^ ((s >> 2) & 15);
        uint4 val = *(const uint4*)&tile[s * 128 + (chunk << 3)];
        *(uint4*)(outp + s * CHN + 8 * c8) = val;
    }
}

// ---------------------------------------------------------------------------
// Gather + basis: half-warp per point, lane owns output channel c = lane&15
// ---------------------------------------------------------------------------
__device__ __forceinline__ void load_corners(const uint4* __restrict__ gb,
                                             int off, uint4* v) {
    v[0] = __ldg(&gb[off]);
    v[1] = __ldg(&gb[off + 16]);       // +x texel
    v[2] = __ldg(&gb[off + 4096]);     // +y row
    v[3] = __ldg(&gb[off + 4112]);
}

__device__ __forceinline__ void blend_plane(const uint4* v, float wxd, float wyd,
                                            float kdd, const float* frh,
                                            float& acc0, float& acc1) {
    __half2 w00 = __float2half2_rn((1.0f - wxd) * (1.0f - wyd));
    __half2 w01 = __float2half2_rn(wxd * (1.0f - wyd));
    __half2 w10 = __float2half2_rn((1.0f - wxd) * wyd);
    __half2 w11 = __float2half2_rn(wxd * wyd);

    const __half2* c0 = (const __half2*)&v[0];
    const __half2* c1 = (const __half2*)&v[1];
    const __half2* c2 = (const __half2*)&v[2];
    const __half2* c3 = (const __half2*)&v[3];

    #pragma unroll
    for (int q = 0; q < 4; q++) {
        __half2 cf = __hmul2(w00, c0[q]);
        cf = __hfma2(w01, c1[q], cf);
        cf = __hfma2(w10, c2[q], cf);
        cf = __hfma2(w11, c3[q], cf);
        float2 f = __half22float2(cf);
        acc0 = fmaf(f.x, __cosf(kdd * frh[2 * q]),     acc0);
        acc1 = fmaf(f.y, __cosf(kdd * frh[2 * q + 1]), acc1);
    }
}

template <int PAIRS>
__global__ void __launch_bounds__(256)
freqgrid_kernel(const float* __restrict__ coords,
                const float* __restrict__ freqs,
                float* __restrict__ out, int N) {
    const int warp = (blockIdx.x * blockDim.x + threadIdx.x) >> 5;
    const int lane = threadIdx.x & 31;
    const int sub  = lane >> 4;     // 0: point A, 1: point B
    const int cl   = lane & 15;     // output channel / uint4 slot

    // Per-lane frequency constants for channels 8*cl + j (amortized over
    // 2*PAIRS points)
    float frh[8];
    #pragma unroll
    for (int j = 0; j < 8; j++) {
        float fq = __ldg(&freqs[8 * cl + j]);
        fq = fminf(fmaxf(fq, 0.0f), 1.0f);
        frh[j] = exp2f(fq * 8.0f) - 0.5f;
    }

    const uint4* __restrict__ gb = (const uint4*)g_grid_t;   // texel = 16 uint4

    const int base0 = warp * (2 * PAIRS);
    #pragma unroll
    for (int t = 0; t < PAIRS; t++) {
        const int nb = base0 + 2 * t;
        if (nb >= N) return;
        const int n = min(nb + sub, N - 1);

        float pt0 = fmaf(coords[3 * n + 0], 127.5f, 127.5f);
        float pt1 = fmaf(coords[3 * n + 1], 127.5f, 127.5f);
        float pt2 = fmaf(coords[3 * n + 2], 127.5f, 127.5f);

        float kd0 = fmaf(pt0, PI_OVER_R, KC);
        float kd1 = fmaf(pt1, PI_OVER_R, KC);
        float kd2 = fmaf(pt2, PI_OVER_R, KC);

        // plane d samples (ix,iy) from pt[{1,0,0}], pt[{2,2,1}]
        // coords in [-1,1) => top-edge corners carry exactly-zero weights;
        // padded grid makes the unclamped reads safe.
        int x0a = (int)pt1, y0a = (int)pt2;        // plane 0
        int x0b = (int)pt0, y0b = (int)pt2;        // plane 1
        int x0c = (int)pt0, y0c = (int)pt1;        // plane 2

        float wxa = pt1 - (float)x0a, wya = pt2 - (float)y0a;
        float wxb = pt0 - (float)x0b, wyb = pt2 - (float)y0b;
        float wxc = pt0 - (float)x0c, wyc = pt1 - (float)y0c;

        int offa = (((y0a << 8) + x0a) << 4) + cl;
        int offb = ((PLANE_ELEMS + (y0b << 8) + x0b) << 4) + cl;
        int offc = ((2 * PLANE_ELEMS + (y0c << 8) + x0c) << 4) + cl;

        float acc0 = 0.0f, acc1 = 0.0f;
        uint4 va[4], vb[4];

        // 2-deep software pipeline over the 3 planes
        load_corners(gb, offa, va);
        load_corners(gb, offb, vb);
        blend_plane(va, wxa, wya, kd0, frh, acc0, acc1);
        load_corners(gb, offc, va);
        blend_plane(vb, wxb, wyb, kd1, frh, acc0, acc1);
        blend_plane(va, wxc, wyc, kd2, frh, acc0, acc1);

        if (nb + sub < N) {
            out[n * 16 + cl] = 2.0f * (acc0 + acc1);
        }
    }
}

// ---------------------------------------------------------------------------
// Harness entry
// ---------------------------------------------------------------------------
extern "C" void kernel_launch(void* const* d_in, const int* in_sizes, int n_in,
                              void* d_out, int out_size) {
    const float* coords = (const float*)d_in[0];
    const float* grid   = (const float*)d_in[1];
    const float* freqs  = (const float*)d_in[2];
    float* out = (float*)d_out;

    const int N = in_sizes[0] / 3;

    dim3 tg(PLANE_ELEMS / 64, 3);
    transpose_kernel<<<tg, 256>>>(grid);

    constexpr int PAIRS = 8;                       // 16 points per warp
    const int pts_per_warp = 2 * PAIRS;
    const int warps = (N + pts_per_warp - 1) / pts_per_warp;
    const int threads = 256;
    const int blocks = (warps * 32 + threads - 1) / threads;
    freqgrid_kernel<PAIRS><<<blocks, threads>>>(coords, freqs, out, N);
}